// round 1
// baseline (speedup 1.0000x reference)
#include <cuda_runtime.h>
#include <math.h>

#define B_     64
#define F_     4097
#define FCL_   65
#define FL_    64
#define IR_    129
#define CONV_  192
#define OUT_S  262144
#define NFRB   32          // frames per block
#define NWARP  8
#define FPW    4           // frames per warp
#define ACCLEN 2176        // (NFRB-1)*64 + 192

// Accurate trig / window tables, filled in double precision each call.
__device__ float g_c65[66];
__device__ float g_s65[66];
__device__ float g_win[130];

__global__ void init_tables_k() {
    int i = threadIdx.x;
    const double TH = 2.0 * 3.141592653589793238462643 / 129.0;
    if (i < 66) {
        g_c65[i] = (float)cos(TH * (double)i);
        g_s65[i] = (float)sin(TH * (double)i);
    }
    if (i < 130) {
        g_win[i] = (float)(0.5 - 0.5 * cos(TH * (double)i));
    }
}

__global__ void zero_out_k(float4* __restrict__ out, int n4) {
    int i = blockIdx.x * blockDim.x + threadIdx.x;
    float4 z = make_float4(0.f, 0.f, 0.f, 0.f);
    for (; i < n4; i += gridDim.x * blockDim.x) out[i] = z;
}

__device__ __forceinline__ float msig(float x) {
    // 2 * sigmoid(x)^ln(10) + 1e-7 ; x in [-1,1] so sigmoid in [0.27,0.73]
    float sg = 1.0f / (1.0f + __expf(-x));
    return 2.0f * __powf(sg, 2.302585092994046f) + 1e-7f;
}

__global__ __launch_bounds__(256) void fn_main(
        const float* __restrict__ coeff,   // (B, F, 65)
        const float* __restrict__ noise,   // (B, F, 64)
        float* __restrict__ out)           // (B, 262144)
{
    __shared__ float cosS[66], sinS[66], winS[130];
    __shared__ float wirb[NWARP][256];   // padded: zeros [0,63] & [193,255], wir at [64..192]
    __shared__ float xsb[NWARP][64];
    __shared__ float sbuf[NWARP][66];
    __shared__ float outb[NFRB][CONV_];  // per-frame conv results

    const int tid = threadIdx.x;
    const int w   = tid >> 5;
    const int l   = tid & 31;
    const int q   = blockIdx.x;          // 0..127 (frames 0..4095; frame 4096 never contributes)
    const int b   = blockIdx.y;
    const int f0  = q * NFRB;

    // Stage tables; zero wir buffers (padding regions stay zero for all frames).
    for (int i = tid; i < 66;  i += 256) { cosS[i] = g_c65[i]; sinS[i] = g_s65[i]; }
    for (int i = tid; i < 130; i += 256) winS[i] = g_win[i];
    for (int i = tid; i < NWARP * 256; i += 256) ((float*)wirb)[i] = 0.f;
    __syncthreads();

    // Per-lane rotation seeds: lane handles t1 = l+1 (1..32), t2 = l+33 (33..64); t=0 shared.
    const int   t1  = l + 1,  t2 = l + 33;
    const float rc1 = cosS[t1], rs1 = sinS[t1];
    const float rc2 = cosS[t2], rs2 = sinS[t2];
    const float w1p = winS[64 + t1], w1m = winS[64 - t1];
    const float w2p = winS[64 + t2], w2m = winS[64 - t2];
    const float wc  = winS[64];

    for (int ff = 0; ff < FPW; ff++) {
        const int fi = ff * NWARP + w;          // 0..31, unique per (ff,w)
        const int f  = f0 + fi;                 // < 4097 always (q<=127 -> f<=4095)

        // ---- load coefficients + noise, apply modified sigmoid / rescale ----
        const float* cp = coeff + ((size_t)b * F_ + f) * FCL_;
        const float* np = noise + ((size_t)b * F_ + f) * FL_;
        sbuf[w][l]      = msig(cp[l]);
        sbuf[w][l + 32] = msig(cp[l + 32]);
        if (l == 0) sbuf[w][64] = msig(cp[64]);
        xsb[w][l]       = 2.f * np[l]      - 1.f;
        xsb[w][l + 32]  = 2.f * np[l + 32] - 1.f;
        __syncwarp();

        // ---- cosine transform (irfft of real spectrum) via stable rotation ----
        // zp[t] = (s0 + 2*sum_{k=1..64} s_k cos(2pi k t/129)) / 129, t = 0..64
        float c1 = rc1, s1 = rs1, c2 = rc2, s2 = rs2;
        float ac0 = 0.f, ac1 = 0.f, ac2 = 0.f;
        const float s0v = sbuf[w][0];
        #pragma unroll 8
        for (int k = 1; k <= 64; k++) {
            const float sk = sbuf[w][k];
            ac0 += sk;
            ac1 += sk * c1;
            ac2 += sk * c2;
            const float nc1 = c1 * rc1 - s1 * rs1;
            const float ns1 = s1 * rc1 + c1 * rs1;
            c1 = nc1; s1 = ns1;
            const float nc2 = c2 * rc2 - s2 * rs2;
            const float ns2 = s2 * rc2 + c2 * rs2;
            c2 = nc2; s2 = ns2;
        }
        const float SCL = 1.0f / 129.0f;
        const float zp0 = (s0v + 2.f * ac0) * SCL;
        const float zp1 = (s0v + 2.f * ac1) * SCL;
        const float zp2 = (s0v + 2.f * ac2) * SCL;

        // ---- windowed linear-phase IR into padded buffer ----
        // lp[j] = zp[(j-64) mod 129]; zp symmetric -> lp[64+d]=lp[64-d]=zp[d]
        float* wb = wirb[w];
        wb[128 + t1] = w1p * zp1;   // j = 64+t1
        wb[128 - t1] = w1m * zp1;   // j = 64-t1
        wb[128 + t2] = w2p * zp2;   // j = 64+t2
        wb[128 - t2] = w2m * zp2;   // j = 64-t2
        if (l == 0) wb[128] = wc * zp0;   // j = 64
        __syncwarp();

        // ---- linear convolution: out[t] = sum_tau x[tau] * wir[t-tau], t=0..191 ----
        float a0 = 0.f, a1 = 0.f, a2 = 0.f, a3 = 0.f, a4 = 0.f, a5 = 0.f;
        #pragma unroll 4
        for (int tau = 0; tau < 64; tau++) {
            const float xv = xsb[w][tau];
            const float* wp = &wb[64 + l - tau];   // index in [1,255]; zeros outside IR
            a0 += xv * wp[0];
            a1 += xv * wp[32];
            a2 += xv * wp[64];
            a3 += xv * wp[96];
            a4 += xv * wp[128];
            a5 += xv * wp[160];
        }
        float* ob = outb[fi];
        ob[l]       = a0;
        ob[l + 32]  = a1;
        ob[l + 64]  = a2;
        ob[l + 96]  = a3;
        ob[l + 128] = a4;
        ob[l + 160] = a5;
        __syncwarp();   // all lanes done with sbuf/xsb/wirb before next frame reuses them
    }

    __syncthreads();

    // ---- overlap-add: gather up to 3 contributing frames per output sample ----
    const size_t rowb = (size_t)b * OUT_S;
    const int gb = f0 * FL_;                  // q * 2048
    for (int p = tid; p < ACCLEN; p += 256) {
        const int P = gb + p;
        if (P >= OUT_S) continue;
        const int fhi = p >> 6;
        const int t0  = p & 63;
        float v = 0.f;
        if (fhi < NFRB)                 v += outb[fhi][t0];
        if (fhi >= 1 && fhi - 1 < NFRB) v += outb[fhi - 1][t0 + 64];
        if (fhi >= 2 && fhi - 2 < NFRB) v += outb[fhi - 2][t0 + 128];
        if (p >= 128 && p < 2048) out[rowb + P] = v;        // exclusively owned
        else                      atomicAdd(&out[rowb + P], v);  // block boundary
    }
}

extern "C" void kernel_launch(void* const* d_in, const int* in_sizes, int n_in,
                              void* d_out, int out_size) {
    const float* coeff = (const float*)d_in[0];
    const float* noise = (const float*)d_in[1];
    float* out = (float*)d_out;

    init_tables_k<<<1, 130>>>();
    zero_out_k<<<4096, 256>>>((float4*)out, (B_ * OUT_S) / 4);
    dim3 grid(128, B_);   // 128 frame-blocks x 64 batch rows; frame 4096 never reaches output
    fn_main<<<grid, 256>>>(coeff, noise, out);
}